// round 15
// baseline (speedup 1.0000x reference)
#include <cuda_runtime.h>
#include <cstdint>
#include <math.h>

#define DIMS   256
#define BATCH  2048
#define NPAIR  32896              // 256*257/2 multiset pairs (i<=j)
#define NROWS  33280              // 260 tiles * 128 rows
#define BM     128
#define BN     256
#define THREADS 256
#define STAGE_BYTES (BM * 32 * 4)                // 16 KB per 32-k chunk
#define SMEM_BYTES  (4 * STAGE_BYTES + BN * 4)   // ring of 4 + sred

// ---- device scratch (allocation-free) ----
// A rows: p = j(j+1)/2 + i for i<=j; S[p][k] = 0 for k<j, multiset-sym sum else.
__device__ float    g_c3p[NROWS * DIMS];         // 34 MB, tf32-rounded
__device__ uint32_t g_pairIdx[NROWS];            // (i<<16)|j per row
// B fragment-major: word = ((ng*16 + kp)*32 + lane)*4 + r
__device__ float    g_relf[BATCH * DIMS];        // 2 MB, tf32-rounded
__device__ float    g_relT[(DIMS + 1) * BATCH];  // rel^T exact; row 256 = 1.0

static __device__ __forceinline__ float f2tf32f(float f) {
    uint32_t r;
    asm("cvt.rna.tf32.f32 %0, %1;" : "=r"(r) : "f"(f));
    return __uint_as_float(r);
}

#define MMA_TF32(C, A0, A1, A2, A3, B0, B1)                                   \
    asm volatile(                                                             \
        "mma.sync.aligned.m16n8k8.row.col.f32.tf32.tf32.f32 "                 \
        "{%0,%1,%2,%3}, {%4,%5,%6,%7}, {%8,%9}, {%0,%1,%2,%3};"               \
        : "+f"((C)[0]), "+f"((C)[1]), "+f"((C)[2]), "+f"((C)[3])              \
        : "r"(A0), "r"(A1), "r"(A2), "r"(A3), "r"(B0), "r"(B1))

#define LDSM4(R, addr)                                                        \
    asm volatile("ldmatrix.sync.aligned.m8n8.x4.shared.b16 {%0,%1,%2,%3}, [%4];" \
        : "=r"((R)[0]), "=r"((R)[1]), "=r"((R)[2]), "=r"((R)[3])              \
        : "r"(addr))

static __device__ __forceinline__ void cp16(uint32_t dst, const void* gsrc) {
    asm volatile("cp.async.cg.shared.global [%0], [%1], 16;"
                 :: "r"(dst), "l"(gsrc) : "memory");
}
#define CP_COMMIT() asm volatile("cp.async.commit_group;" ::: "memory")
#define CP_WAIT2()  asm volatile("cp.async.wait_group 2;" ::: "memory")

static __device__ __forceinline__ uint32_t smem_u32(const void* p) {
    uint32_t a;
    asm("{ .reg .u64 t; cvta.to.shared.u64 t, %1; cvt.u32.u64 %0, t; }" : "=r"(a) : "l"(p));
    return a;
}

// ---------------------------------------------------------------------------
// Prep: g_relf fragments + g_relT weights + out init
// ---------------------------------------------------------------------------
__global__ void prep_rel_kernel(const float* __restrict__ x,
                                const float* __restrict__ offsets,
                                const float* __restrict__ c0p,
                                float* __restrict__ out) {
    int idx = blockIdx.x * blockDim.x + threadIdx.x;   // k*BATCH + b
    int k = idx / BATCH;
    int b = idx % BATCH;
    if (k < DIMS) {
        float r = x[b * DIMS + k] - offsets[k];
        g_relT[idx] = r;
        int ng = b >> 3, kp = k >> 4;
        int lane = (b & 7) * 4 + (k & 3);
        int rr = (((k >> 3) & 1) << 1) | ((k & 7) >> 2);
        ((uint32_t*)g_relf)[((ng * 16 + kp) * 32 + lane) * 4 + rr] =
            __float_as_uint(f2tf32f(r));
    } else {
        g_relT[idx] = 1.0f;
        out[b] = c0p[0];
    }
}

// ---------------------------------------------------------------------------
// pack3: full 3-index symmetrization into pair-rows with ragged K support.
// ---------------------------------------------------------------------------
__global__ void __launch_bounds__(256) pack3_kernel(const float* __restrict__ c3) {
    extern __shared__ float cub[];               // 6 * 4096 floats
    int pr = blockIdx.x;                          // 0..135, (I<=J) ranges
    int J = (int)((sqrtf(8.f * pr + 1.f) - 1.f) * 0.5f);
    while ((J + 1) * (J + 2) / 2 <= pr) J++;
    while (J * (J + 1) / 2 > pr) J--;
    int I = pr - J * (J + 1) / 2;
    int kr = blockIdx.y;                          // 0..15
    const int i0 = I * 16, j0 = J * 16, k0 = kr * 16;
    const int t = threadIdx.x;
    const int il = t >> 4, jl = t & 15;
    const int i = i0 + il, j = j0 + jl;
    const bool valid = (i <= j);
    const int p = (j * (j + 1)) / 2 + i;
    float* outrow = g_c3p + (size_t)p * DIMS + k0;
    if (valid && kr == 0) g_pairIdx[p] = ((uint32_t)i << 16) | (uint32_t)j;

    if (k0 + 15 < j0) {                           // whole block k < j: zeros
        if (valid) {
            float4 z = make_float4(0.f, 0.f, 0.f, 0.f);
            *(float4*)(outrow + 0) = z;  *(float4*)(outrow + 4) = z;
            *(float4*)(outrow + 8) = z;  *(float4*)(outrow + 12) = z;
        }
        return;
    }

    const int R0[6] = { I, I, J, J, kr, kr };
    const int R1[6] = { J, kr, I, kr, I, J };
    const int R2[6] = { kr, J, kr, I, J, I };
#pragma unroll
    for (int m = 0; m < 6; m++) {
        const float* src = c3 + ((size_t)(R0[m] * 16 + il) * 65536)
                              + (R1[m] * 16 + jl) * 256 + R2[m] * 16;
        float* dst = cub + m * 4096 + il * 256 + jl * 16;
#pragma unroll
        for (int r4 = 0; r4 < 4; r4++) {
            float4 v = *(const float4*)(src + r4 * 4);
            dst[r4 * 4 + 0] = v.x; dst[r4 * 4 + 1] = v.y;
            dst[r4 * 4 + 2] = v.z; dst[r4 * 4 + 3] = v.w;
        }
    }
    __syncthreads();
    if (!valid) return;

    float S[16];
#pragma unroll
    for (int kl = 0; kl < 16; kl++) {
        int k = k0 + kl;
        float s;
        if (k < j) {
            s = 0.f;
        } else {
            float C1 = cub[0 * 4096 + il * 256 + jl * 16 + kl];   // c3[i,j,k]
            if (k == j) {
                if (i == j) s = C1;
                else s = C1
                       + cub[2 * 4096 + jl * 256 + il * 16 + kl]  // c3[j,i,k]
                       + cub[3 * 4096 + jl * 256 + kl * 16 + il]; // c3[j,k,i]
            } else {
                float C2 = cub[1 * 4096 + il * 256 + kl * 16 + jl]; // c3[i,k,j]
                float C5 = cub[4 * 4096 + kl * 256 + il * 16 + jl]; // c3[k,i,j]
                if (i == j) s = C1 + C2 + C5;
                else s = C1 + C2 + C5
                       + cub[2 * 4096 + jl * 256 + il * 16 + kl]
                       + cub[3 * 4096 + jl * 256 + kl * 16 + il]
                       + cub[5 * 4096 + kl * 256 + jl * 16 + il];   // c3[k,j,i]
            }
        }
        S[kl] = f2tf32f(s);
    }
    *(float4*)(outrow + 0)  = *(float4*)&S[0];
    *(float4*)(outrow + 4)  = *(float4*)&S[4];
    *(float4*)(outrow + 8)  = *(float4*)&S[8];
    *(float4*)(outrow + 12) = *(float4*)&S[12];
}

// ---------------------------------------------------------------------------
// extras: c2 rows (weight r_j*1), c1 row (1*1), zero pads — full K support.
// ---------------------------------------------------------------------------
__global__ void extras_kernel(const float* __restrict__ c2,
                              const float* __restrict__ c1) {
    int r = blockIdx.x;            // 0..383
    int k = threadIdx.x;           // 0..255
    int p = NPAIR + r;
    float v;
    uint32_t pidx;
    if (r < 256)      { v = c2[r * DIMS + k]; pidx = (256u << 16) | (uint32_t)r; }
    else if (r == 256){ v = c1[k];            pidx = (256u << 16) | 256u; }
    else              { v = 0.f;              pidx = (256u << 16) | 256u; }
    g_c3p[(size_t)p * DIMS + k] = f2tf32f(v);
    if (k == 0) g_pairIdx[p] = pidx;
}

// ---------------------------------------------------------------------------
// Main: 256 threads, 8 warps = 2M x 4N (64x64 warp tiles — L1-optimal).
// A: cp.async 4-stage ring with per-tile chunk skipping; B: direct GMEM
// fragments double-buffered. LPT tile remap (full-K extras first).
// ---------------------------------------------------------------------------
__global__ void __launch_bounds__(THREADS) taylor_mma_kernel(
    float* __restrict__ out) {

    extern __shared__ char smem[];
    const uint32_t sb = smem_u32(smem);
    float* sred = (float*)(smem + 4 * STAGE_BYTES);

    const int tid  = threadIdx.x;
    const int lane = tid & 31, wid = tid >> 5;
    const int warpM = wid & 1, warpN = wid >> 1;   // 2 x 4 warps
    const int g = lane >> 2, tig = lane & 3;

    int tile = blockIdx.x - 3;                     // extras tiles first (LPT)
    if (tile < 0) tile += 260;
    const int p0 = tile * BM;
    const int b0 = blockIdx.y * BN;

    // per-tile chunk start: c0 = floor(j_min / 32)
    int c0 = 0;
    if (tile < 257) {
        int r0 = tile * BM;
        int j0 = (int)((sqrtf(8.f * r0 + 1.f) - 1.f) * 0.5f);
        while ((j0 + 1) * (j0 + 2) / 2 <= r0) j0++;
        while (j0 * (j0 + 1) / 2 > r0) j0--;
        c0 = j0 >> 5;
    }

    sred[tid] = 0.f;                               // BN == 256 == blockDim

    // ---- A cp.async coords (16KB chunk, 256 thr => 4 cp16/thread) ----
    const float* Ag = g_c3p + (size_t)p0 * DIMS;
    uint32_t cpdst[4];
    const float* cpsrc[4];
#pragma unroll
    for (int it = 0; it < 4; it++) {
        int idx = tid + it * THREADS;
        int row = idx >> 3, seg = idx & 7;
        cpdst[it] = row * 128 + ((seg ^ (row & 7)) << 4);
        cpsrc[it] = Ag + (size_t)row * DIMS + seg * 4;
    }
    auto cp_chunk = [&](int c, int stage) {
        const uint32_t s = sb + stage * STAGE_BYTES;
        const int k0 = c * 32;
#pragma unroll
        for (int it = 0; it < 4; it++)
            cp16(s + cpdst[it], cpsrc[it] + k0);
    };

    // ---- B fragment pointer; 8 n-slots per warp (warp tile N=64) ----
    const uint4* bptr = (const uint4*)g_relf
                      + ((size_t)(b0 >> 3) + warpN * 8) * 512 + lane;

    // ---- LDSM addressing, 4 msl (warp tile M=64) ----
    int aoff[4], axor[4];
#pragma unroll
    for (int msl = 0; msl < 4; msl++) {
        int rowA = warpM * 64 + msl * 16 + ((lane >> 3) & 1) * 8 + (lane & 7);
        aoff[msl] = rowA * 128;
        axor[msl] = rowA & 7;
    }
    const int kcA = (lane >> 4) & 1;

    float acc[4][8][4];
#pragma unroll
    for (int m = 0; m < 4; m++)
#pragma unroll
        for (int n = 0; n < 8; n++)
#pragma unroll
            for (int r = 0; r < 4; r++) acc[m][n][r] = 0.f;

    uint4 Bb0[8], Bb1[8];

    // prologue: up to 3 chunks in flight (always 3 commits)
#pragma unroll
    for (int tq = 0; tq < 3; tq++) {
        if (c0 + tq < 8) cp_chunk(c0 + tq, (c0 + tq) & 3);
        CP_COMMIT();
    }

#define LDB(BB, kp)                                                           \
    do {                                                                      \
        _Pragma("unroll")                                                     \
        for (int nsl_ = 0; nsl_ < 8; nsl_++)                                  \
            (BB)[nsl_] = __ldg(bptr + nsl_ * 512 + (kp) * 32);                \
    } while (0)

#define COMPUTE_KP(As, KSBASE, BB)                                            \
    do {                                                                      \
        _Pragma("unroll")                                                     \
        for (int ks2 = 0; ks2 < 2; ++ks2) {                                   \
            const int ks = (KSBASE) + ks2;                                    \
            uint32_t a[4][4];                                                 \
            _Pragma("unroll")                                                 \
            for (int msl = 0; msl < 4; ++msl)                                 \
                LDSM4(a[msl], (As) + aoff[msl] +                              \
                      ((((ks << 1) | kcA) ^ axor[msl]) << 4));                \
            _Pragma("unroll")                                                 \
            for (int nsl = 0; nsl < 8; ++nsl) {                               \
                uint32_t b0v = ks2 ? (BB)[nsl].z : (BB)[nsl].x;               \
                uint32_t b1v = ks2 ? (BB)[nsl].w : (BB)[nsl].y;               \
                _Pragma("unroll")                                             \
                for (int msl = 0; msl < 4; ++msl)                             \
                    MMA_TF32(acc[msl][nsl], a[msl][0], a[msl][1],             \
                             a[msl][2], a[msl][3], b0v, b1v);                 \
            }                                                                 \
        }                                                                     \
    } while (0)

    LDB(Bb0, 2 * c0);

    for (int cc = c0; cc < 8; ++cc) {
        CP_WAIT2();
        __syncthreads();
        if (cc + 3 < 8) cp_chunk(cc + 3, (cc + 3) & 3);
        CP_COMMIT();

        const uint32_t As = sb + (cc & 3) * STAGE_BYTES;
        const int s0 = 2 * cc;

        LDB(Bb1, s0 + 1);
        COMPUTE_KP(As, 0, Bb0);
        if (cc + 1 < 8) LDB(Bb0, s0 + 2);
        COMPUTE_KP(As, 2, Bb1);
    }

    // ---- epilogue: sred[col] += sum_m D[m,col] * r_i(m)[b] * r_j(m)[b] ----
    const float* wi[4][2];
    const float* wj[4][2];
#pragma unroll
    for (int msl = 0; msl < 4; ++msl)
#pragma unroll
        for (int h = 0; h < 2; ++h) {
            int rloc = warpM * 64 + msl * 16 + h * 8 + g;
            uint32_t pij = g_pairIdx[p0 + rloc];
            wi[msl][h] = g_relT + (size_t)(pij >> 16) * BATCH + b0;
            wj[msl][h] = g_relT + (size_t)(pij & 0xFFFF) * BATCH + b0;
        }

#pragma unroll
    for (int nsl = 0; nsl < 8; ++nsl) {
        const int coln = warpN * 64 + nsl * 8 + tig * 2;
        float s0 = 0.f, s1 = 0.f;
#pragma unroll
        for (int msl = 0; msl < 4; ++msl) {
#pragma unroll
            for (int h = 0; h < 2; ++h) {
                float2 aw = *(const float2*)(wi[msl][h] + coln);
                float2 bw = *(const float2*)(wj[msl][h] + coln);
                s0 += acc[msl][nsl][2 * h]     * aw.x * bw.x;
                s1 += acc[msl][nsl][2 * h + 1] * aw.y * bw.y;
            }
        }
#pragma unroll
        for (int o = 4; o <= 16; o <<= 1) {
            s0 += __shfl_xor_sync(0xFFFFFFFFu, s0, o);
            s1 += __shfl_xor_sync(0xFFFFFFFFu, s1, o);
        }
        if (g == 0) {
            atomicAdd(&sred[coln],     s0);
            atomicAdd(&sred[coln + 1], s1);
        }
    }
    __syncthreads();

    atomicAdd(out + b0 + tid, sred[tid]);
}

// ---------------------------------------------------------------------------
extern "C" void kernel_launch(void* const* d_in, const int* in_sizes, int n_in,
                              void* d_out, int out_size) {
    const float* x       = (const float*)d_in[0];
    const float* offsets = (const float*)d_in[1];
    const float* coeff0  = (const float*)d_in[2];
    const float* coeff1  = (const float*)d_in[3];
    const float* coeff2  = (const float*)d_in[4];
    const float* coeff3  = (const float*)d_in[5];
    float* out = (float*)d_out;

    cudaFuncSetAttribute(taylor_mma_kernel,
                         cudaFuncAttributeMaxDynamicSharedMemorySize, SMEM_BYTES);
    cudaFuncSetAttribute(pack3_kernel,
                         cudaFuncAttributeMaxDynamicSharedMemorySize, 98304);

    prep_rel_kernel<<<((DIMS + 1) * BATCH) / 256, 256>>>(x, offsets, coeff0, out);

    dim3 pgrid(136, 16);
    pack3_kernel<<<pgrid, 256, 98304>>>(coeff3);
    extras_kernel<<<384, 256>>>(coeff2, coeff1);

    dim3 grid(NROWS / BM, BATCH / BN);   // (260, 8)
    taylor_mma_kernel<<<grid, THREADS, SMEM_BYTES>>>(out);
}

// round 16
// speedup vs baseline: 1.1361x; 1.1361x over previous
#include <cuda_runtime.h>
#include <cstdint>
#include <math.h>

#define DIMS   256
#define BATCH  2048
#define NPAIR  32896              // 256*257/2 multiset pairs (i<=j)
#define NROWS  33280              // 260 tiles * 128 rows
#define BM     128
#define BN     256
#define THREADS 512
#define STAGE_BYTES (BM * 32 * 4)                // 16 KB per 32-k chunk
#define SMEM_BYTES  (4 * STAGE_BYTES + BN * 4)   // ring of 4 + sred

// ---- device scratch (allocation-free) ----
__device__ float    g_c3p[NROWS * DIMS];         // 34 MB, tf32-rounded
__device__ uint32_t g_pairIdx[NROWS];            // (i<<16)|j per row
__device__ float    g_relf[BATCH * DIMS];        // 2 MB, tf32-rounded
__device__ float    g_relT[(DIMS + 1) * BATCH];  // rel^T exact; row 256 = 1.0

static __device__ __forceinline__ float f2tf32f(float f) {
    uint32_t r;
    asm("cvt.rna.tf32.f32 %0, %1;" : "=r"(r) : "f"(f));
    return __uint_as_float(r);
}

#define MMA_TF32(C, A0, A1, A2, A3, B0, B1)                                   \
    asm volatile(                                                             \
        "mma.sync.aligned.m16n8k8.row.col.f32.tf32.tf32.f32 "                 \
        "{%0,%1,%2,%3}, {%4,%5,%6,%7}, {%8,%9}, {%0,%1,%2,%3};"               \
        : "+f"((C)[0]), "+f"((C)[1]), "+f"((C)[2]), "+f"((C)[3])              \
        : "r"(A0), "r"(A1), "r"(A2), "r"(A3), "r"(B0), "r"(B1))

#define LDSM4(R, addr)                                                        \
    asm volatile("ldmatrix.sync.aligned.m8n8.x4.shared.b16 {%0,%1,%2,%3}, [%4];" \
        : "=r"((R)[0]), "=r"((R)[1]), "=r"((R)[2]), "=r"((R)[3])              \
        : "r"(addr))

static __device__ __forceinline__ void cp16(uint32_t dst, const void* gsrc) {
    asm volatile("cp.async.cg.shared.global [%0], [%1], 16;"
                 :: "r"(dst), "l"(gsrc) : "memory");
}
#define CP_COMMIT() asm volatile("cp.async.commit_group;" ::: "memory")
#define CP_WAIT2()  asm volatile("cp.async.wait_group 2;" ::: "memory")

static __device__ __forceinline__ uint32_t smem_u32(const void* p) {
    uint32_t a;
    asm("{ .reg .u64 t; cvta.to.shared.u64 t, %1; cvt.u32.u64 %0, t; }" : "=r"(a) : "l"(p));
    return a;
}

// ---------------------------------------------------------------------------
// Prep: g_relf fragments + g_relT weights + out init
// ---------------------------------------------------------------------------
__global__ void prep_rel_kernel(const float* __restrict__ x,
                                const float* __restrict__ offsets,
                                const float* __restrict__ c0p,
                                float* __restrict__ out) {
    int idx = blockIdx.x * blockDim.x + threadIdx.x;   // k*BATCH + b
    int k = idx / BATCH;
    int b = idx % BATCH;
    if (k < DIMS) {
        float r = x[b * DIMS + k] - offsets[k];
        g_relT[idx] = r;
        int ng = b >> 3, kp = k >> 4;
        int lane = (b & 7) * 4 + (k & 3);
        int rr = (((k >> 3) & 1) << 1) | ((k & 7) >> 2);
        ((uint32_t*)g_relf)[((ng * 16 + kp) * 32 + lane) * 4 + rr] =
            __float_as_uint(f2tf32f(r));
    } else {
        g_relT[idx] = 1.0f;
        out[b] = c0p[0];
    }
}

// ---------------------------------------------------------------------------
// pack3 (k-width 8): full 3-index symmetrization, 6 x 8KB permuted cubes in
// 48KB SMEM -> 4 CTAs/SM.  Block = (pair-range pr, k-range kr in 8s).
// ---------------------------------------------------------------------------
__global__ void __launch_bounds__(256) pack3_kernel(const float* __restrict__ c3) {
    extern __shared__ float cub[];               // 6 * 2048 floats = 48 KB
    int pr = blockIdx.x;                          // 0..135 (I<=J ranges)
    int J = (int)((sqrtf(8.f * pr + 1.f) - 1.f) * 0.5f);
    while ((J + 1) * (J + 2) / 2 <= pr) J++;
    while (J * (J + 1) / 2 > pr) J--;
    int I = pr - J * (J + 1) / 2;
    int kr = blockIdx.y;                          // 0..31 (8-wide)
    const int i0 = I * 16, j0 = J * 16, k0 = kr * 8;
    const int t = threadIdx.x;
    const int il = t >> 4, jl = t & 15;
    const int i = i0 + il, j = j0 + jl;
    const bool valid = (i <= j);
    const int p = (j * (j + 1)) / 2 + i;
    float* outrow = g_c3p + (size_t)p * DIMS + k0;
    if (valid && kr == 0) g_pairIdx[p] = ((uint32_t)i << 16) | (uint32_t)j;

    if (k0 + 7 < j0) {                            // whole block k < j: zeros
        if (valid) {
            float4 z = make_float4(0.f, 0.f, 0.f, 0.f);
            *(float4*)(outrow + 0) = z;
            *(float4*)(outrow + 4) = z;
        }
        return;
    }

    // 6 permuted cubes; smem layout [d0][d1][d2] linear, d2 = c3's stride-1 axis
    // m:   axes (d0,d1,d2) widths       c3 coord bases (a,b,c)
    // 0: (i,j,k) (16,16,8)   (i0,j0,k0)
    // 1: (i,k,j) (16, 8,16)  (i0,k0,j0)
    // 2: (j,i,k) (16,16,8)   (j0,i0,k0)
    // 3: (j,k,i) (16, 8,16)  (j0,k0,i0)
    // 4: (k,i,j) ( 8,16,16)  (k0,i0,j0)
    // 5: (k,j,i) ( 8,16,16)  (k0,j0,i0)
    {
        const int W1[6] = { 16, 8, 16, 8, 16, 16 };
        const int W2[6] = { 8, 16, 8, 16, 16, 16 };
        const int BA[6] = { i0, i0, j0, j0, k0, k0 };
        const int BB[6] = { j0, k0, i0, k0, i0, j0 };
        const int BC[6] = { k0, j0, k0, i0, j0, i0 };
#pragma unroll
        for (int m = 0; m < 6; m++) {
            int d0, d1, d2;
            if (W2[m] == 8) { d2 = 0; d1 = t & 15; d0 = t >> 4; }
            else { d2 = (t & 1) * 8; int q = t >> 1;
                   d1 = q % W1[m]; d0 = q / W1[m]; }
            const float* src = c3 + (size_t)(BA[m] + d0) * 65536
                                  + (BB[m] + d1) * 256 + (BC[m] + d2);
            float* dst = cub + m * 2048 + t * 8;
            float4 v0 = *(const float4*)(src);
            float4 v1 = *(const float4*)(src + 4);
            *(float4*)(dst)     = v0;
            *(float4*)(dst + 4) = v1;
        }
    }
    __syncthreads();
    if (!valid) return;

    float S[8];
#pragma unroll
    for (int kl = 0; kl < 8; kl++) {
        int k = k0 + kl;
        float s;
        if (k < j) {
            s = 0.f;
        } else {
            float C1 = cub[0 * 2048 + (il * 16 + jl) * 8 + kl];     // c3[i,j,k]
            if (k == j) {
                if (i == j) s = C1;
                else s = C1
                       + cub[2 * 2048 + (jl * 16 + il) * 8 + kl]    // c3[j,i,k]
                       + cub[3 * 2048 + (jl * 8 + kl) * 16 + il];   // c3[j,k,i]
            } else {
                float C2 = cub[1 * 2048 + (il * 8 + kl) * 16 + jl];   // c3[i,k,j]
                float C5 = cub[4 * 2048 + (kl * 16 + il) * 16 + jl];  // c3[k,i,j]
                if (i == j) s = C1 + C2 + C5;
                else s = C1 + C2 + C5
                       + cub[2 * 2048 + (jl * 16 + il) * 8 + kl]      // c3[j,i,k]
                       + cub[3 * 2048 + (jl * 8 + kl) * 16 + il]      // c3[j,k,i]
                       + cub[5 * 2048 + (kl * 16 + jl) * 16 + il];    // c3[k,j,i]
            }
        }
        S[kl] = f2tf32f(s);
    }
    *(float4*)(outrow + 0) = *(float4*)&S[0];
    *(float4*)(outrow + 4) = *(float4*)&S[4];
}

// ---------------------------------------------------------------------------
// extras: c2 rows (weight r_j*1), c1 row (1*1), zero pads — full K support.
// ---------------------------------------------------------------------------
__global__ void extras_kernel(const float* __restrict__ c2,
                              const float* __restrict__ c1) {
    int r = blockIdx.x;            // 0..383
    int k = threadIdx.x;           // 0..255
    int p = NPAIR + r;
    float v;
    uint32_t pidx;
    if (r < 256)      { v = c2[r * DIMS + k]; pidx = (256u << 16) | (uint32_t)r; }
    else if (r == 256){ v = c1[k];            pidx = (256u << 16) | 256u; }
    else              { v = 0.f;              pidx = (256u << 16) | 256u; }
    g_c3p[(size_t)p * DIMS + k] = f2tf32f(v);
    if (k == 0) g_pairIdx[p] = pidx;
}

// ---------------------------------------------------------------------------
// Main (R14 verbatim — measured 131.7us): 512 thr, 16 warps 2Mx8N (64x32
// warp tiles). A: cp.async 4-stage ring + chunk skipping; B: GMEM fragments.
// ---------------------------------------------------------------------------
__global__ void __launch_bounds__(THREADS) taylor_mma_kernel(
    float* __restrict__ out) {

    extern __shared__ char smem[];
    const uint32_t sb = smem_u32(smem);
    float* sred = (float*)(smem + 4 * STAGE_BYTES);

    const int tid  = threadIdx.x;
    const int lane = tid & 31, wid = tid >> 5;
    const int warpM = wid & 1, warpN = wid >> 1;   // 2 x 8 warps
    const int g = lane >> 2, tig = lane & 3;

    int tile = blockIdx.x - 3;                     // extras tiles first (LPT)
    if (tile < 0) tile += 260;
    const int p0 = tile * BM;
    const int b0 = blockIdx.y * BN;

    int c0 = 0;
    if (tile < 257) {
        int r0 = tile * BM;
        int j0 = (int)((sqrtf(8.f * r0 + 1.f) - 1.f) * 0.5f);
        while ((j0 + 1) * (j0 + 2) / 2 <= r0) j0++;
        while (j0 * (j0 + 1) / 2 > r0) j0--;
        c0 = j0 >> 5;
    }

    if (tid < BN) sred[tid] = 0.f;

    const float* Ag = g_c3p + (size_t)p0 * DIMS;
    uint32_t cpdst[2];
    const float* cpsrc[2];
#pragma unroll
    for (int it = 0; it < 2; it++) {
        int idx = tid + it * THREADS;
        int row = idx >> 3, seg = idx & 7;
        cpdst[it] = row * 128 + ((seg ^ (row & 7)) << 4);
        cpsrc[it] = Ag + (size_t)row * DIMS + seg * 4;
    }
    auto cp_chunk = [&](int c, int stage) {
        const uint32_t s = sb + stage * STAGE_BYTES;
        const int k0 = c * 32;
#pragma unroll
        for (int it = 0; it < 2; it++)
            cp16(s + cpdst[it], cpsrc[it] + k0);
    };

    const uint4* bptr = (const uint4*)g_relf
                      + ((size_t)(b0 >> 3) + warpN * 4) * 512 + lane;

    int aoff[4], axor[4];
#pragma unroll
    for (int msl = 0; msl < 4; msl++) {
        int rowA = warpM * 64 + msl * 16 + ((lane >> 3) & 1) * 8 + (lane & 7);
        aoff[msl] = rowA * 128;
        axor[msl] = rowA & 7;
    }
    const int kcA = (lane >> 4) & 1;

    float acc[4][4][4];
#pragma unroll
    for (int m = 0; m < 4; m++)
#pragma unroll
        for (int n = 0; n < 4; n++)
#pragma unroll
            for (int r = 0; r < 4; r++) acc[m][n][r] = 0.f;

    uint4 Bb0[4], Bb1[4];

#pragma unroll
    for (int tq = 0; tq < 3; tq++) {
        if (c0 + tq < 8) cp_chunk(c0 + tq, (c0 + tq) & 3);
        CP_COMMIT();
    }

#define LDB(BB, kp)                                                           \
    do {                                                                      \
        _Pragma("unroll")                                                     \
        for (int nsl_ = 0; nsl_ < 4; nsl_++)                                  \
            (BB)[nsl_] = __ldg(bptr + nsl_ * 512 + (kp) * 32);                \
    } while (0)

#define COMPUTE_KP(As, KSBASE, BB)                                            \
    do {                                                                      \
        _Pragma("unroll")                                                     \
        for (int ks2 = 0; ks2 < 2; ++ks2) {                                   \
            const int ks = (KSBASE) + ks2;                                    \
            uint32_t a[4][4];                                                 \
            _Pragma("unroll")                                                 \
            for (int msl = 0; msl < 4; ++msl)                                 \
                LDSM4(a[msl], (As) + aoff[msl] +                              \
                      ((((ks << 1) | kcA) ^ axor[msl]) << 4));                \
            _Pragma("unroll")                                                 \
            for (int nsl = 0; nsl < 4; ++nsl) {                               \
                uint32_t b0v = ks2 ? (BB)[nsl].z : (BB)[nsl].x;               \
                uint32_t b1v = ks2 ? (BB)[nsl].w : (BB)[nsl].y;               \
                _Pragma("unroll")                                             \
                for (int msl = 0; msl < 4; ++msl)                             \
                    MMA_TF32(acc[msl][nsl], a[msl][0], a[msl][1],             \
                             a[msl][2], a[msl][3], b0v, b1v);                 \
            }                                                                 \
        }                                                                     \
    } while (0)

    LDB(Bb0, 2 * c0);

    for (int cc = c0; cc < 8; ++cc) {
        CP_WAIT2();
        __syncthreads();
        if (cc + 3 < 8) cp_chunk(cc + 3, (cc + 3) & 3);
        CP_COMMIT();

        const uint32_t As = sb + (cc & 3) * STAGE_BYTES;
        const int s0 = 2 * cc;

        LDB(Bb1, s0 + 1);
        COMPUTE_KP(As, 0, Bb0);
        if (cc + 1 < 8) LDB(Bb0, s0 + 2);
        COMPUTE_KP(As, 2, Bb1);
    }

    const float* wi[4][2];
    const float* wj[4][2];
#pragma unroll
    for (int msl = 0; msl < 4; ++msl)
#pragma unroll
        for (int h = 0; h < 2; ++h) {
            int rloc = warpM * 64 + msl * 16 + h * 8 + g;
            uint32_t pij = g_pairIdx[p0 + rloc];
            wi[msl][h] = g_relT + (size_t)(pij >> 16) * BATCH + b0;
            wj[msl][h] = g_relT + (size_t)(pij & 0xFFFF) * BATCH + b0;
        }

#pragma unroll
    for (int nsl = 0; nsl < 4; ++nsl) {
        const int coln = warpN * 32 + nsl * 8 + tig * 2;
        float s0 = 0.f, s1 = 0.f;
#pragma unroll
        for (int msl = 0; msl < 4; ++msl) {
#pragma unroll
            for (int h = 0; h < 2; ++h) {
                float2 aw = *(const float2*)(wi[msl][h] + coln);
                float2 bw = *(const float2*)(wj[msl][h] + coln);
                s0 += acc[msl][nsl][2 * h]     * aw.x * bw.x;
                s1 += acc[msl][nsl][2 * h + 1] * aw.y * bw.y;
            }
        }
#pragma unroll
        for (int o = 4; o <= 16; o <<= 1) {
            s0 += __shfl_xor_sync(0xFFFFFFFFu, s0, o);
            s1 += __shfl_xor_sync(0xFFFFFFFFu, s1, o);
        }
        if (g == 0) {
            atomicAdd(&sred[coln],     s0);
            atomicAdd(&sred[coln + 1], s1);
        }
    }
    __syncthreads();

    if (tid < BN) atomicAdd(out + b0 + tid, sred[tid]);
}

// ---------------------------------------------------------------------------
extern "C" void kernel_launch(void* const* d_in, const int* in_sizes, int n_in,
                              void* d_out, int out_size) {
    const float* x       = (const float*)d_in[0];
    const float* offsets = (const float*)d_in[1];
    const float* coeff0  = (const float*)d_in[2];
    const float* coeff1  = (const float*)d_in[3];
    const float* coeff2  = (const float*)d_in[4];
    const float* coeff3  = (const float*)d_in[5];
    float* out = (float*)d_out;

    cudaFuncSetAttribute(taylor_mma_kernel,
                         cudaFuncAttributeMaxDynamicSharedMemorySize, SMEM_BYTES);
    cudaFuncSetAttribute(pack3_kernel,
                         cudaFuncAttributeMaxDynamicSharedMemorySize, 49152);

    prep_rel_kernel<<<((DIMS + 1) * BATCH) / 256, 256>>>(x, offsets, coeff0, out);

    dim3 pgrid(136, 32);
    pack3_kernel<<<pgrid, 256, 49152>>>(coeff3);
    extras_kernel<<<384, 256>>>(coeff2, coeff1);

    dim3 grid(NROWS / BM, BATCH / BN);   // (260, 8)
    taylor_mma_kernel<<<grid, THREADS, SMEM_BYTES>>>(out);
}

// round 17
// speedup vs baseline: 1.1669x; 1.0272x over previous
#include <cuda_runtime.h>
#include <cstdint>
#include <math.h>

#define DIMS   256
#define BATCH  2048
#define NPAIR  32896              // 256*257/2 multiset pairs (i<=j)
#define NROWS  33280              // 260 tiles * 128 rows
#define BM     128
#define BN     256
#define THREADS 512
#define CHUNK_BYTES 16384                        // one 32-k chunk
#define PSTAGE_BYTES (2 * CHUNK_BYTES)           // 64 KB: pair of chunks
#define SMEM_BYTES  (3 * PSTAGE_BYTES + BN * 4)  // 3-stage ring + sred

// ---- device scratch (allocation-free) ----
__device__ float    g_c3p[NROWS * DIMS];         // 34 MB, tf32-rounded
__device__ uint32_t g_pairIdx[NROWS];            // (i<<16)|j per row
__device__ float    g_relf[BATCH * DIMS];        // 2 MB, tf32-rounded
__device__ float    g_relT[(DIMS + 1) * BATCH];  // rel^T exact; row 256 = 1.0

static __device__ __forceinline__ float f2tf32f(float f) {
    uint32_t r;
    asm("cvt.rna.tf32.f32 %0, %1;" : "=r"(r) : "f"(f));
    return __uint_as_float(r);
}

#define MMA_TF32(C, A0, A1, A2, A3, B0, B1)                                   \
    asm volatile(                                                             \
        "mma.sync.aligned.m16n8k8.row.col.f32.tf32.tf32.f32 "                 \
        "{%0,%1,%2,%3}, {%4,%5,%6,%7}, {%8,%9}, {%0,%1,%2,%3};"               \
        : "+f"((C)[0]), "+f"((C)[1]), "+f"((C)[2]), "+f"((C)[3])              \
        : "r"(A0), "r"(A1), "r"(A2), "r"(A3), "r"(B0), "r"(B1))

#define LDSM4(R, addr)                                                        \
    asm volatile("ldmatrix.sync.aligned.m8n8.x4.shared.b16 {%0,%1,%2,%3}, [%4];" \
        : "=r"((R)[0]), "=r"((R)[1]), "=r"((R)[2]), "=r"((R)[3])              \
        : "r"(addr))

static __device__ __forceinline__ void cp16(uint32_t dst, const void* gsrc) {
    asm volatile("cp.async.cg.shared.global [%0], [%1], 16;"
                 :: "r"(dst), "l"(gsrc) : "memory");
}
#define CP_COMMIT() asm volatile("cp.async.commit_group;" ::: "memory")
#define CP_WAIT(n)  asm volatile("cp.async.wait_group %0;" :: "n"(n) : "memory")

static __device__ __forceinline__ uint32_t smem_u32(const void* p) {
    uint32_t a;
    asm("{ .reg .u64 t; cvta.to.shared.u64 t, %1; cvt.u32.u64 %0, t; }" : "=r"(a) : "l"(p));
    return a;
}

// ---------------------------------------------------------------------------
// Prep: g_relf fragments + g_relT weights + out init
// ---------------------------------------------------------------------------
__global__ void prep_rel_kernel(const float* __restrict__ x,
                                const float* __restrict__ offsets,
                                const float* __restrict__ c0p,
                                float* __restrict__ out) {
    int idx = blockIdx.x * blockDim.x + threadIdx.x;   // k*BATCH + b
    int k = idx >> 11;
    int b = idx & (BATCH - 1);
    if (k < DIMS) {
        float r = x[b * DIMS + k] - offsets[k];
        g_relT[idx] = r;
        int ng = b >> 3, kp = k >> 4;
        int lane = (b & 7) * 4 + (k & 3);
        int rr = (((k >> 3) & 1) << 1) | ((k & 7) >> 2);
        ((uint32_t*)g_relf)[((ng * 16 + kp) * 32 + lane) * 4 + rr] =
            __float_as_uint(f2tf32f(r));
    } else {
        g_relT[idx] = 1.0f;
        out[b] = c0p[0];
    }
}

// ---------------------------------------------------------------------------
// pack3 (k-width 8): full 3-index symmetrization, 6 x 8KB permuted cubes in
// 48KB SMEM -> 4 CTAs/SM.
// ---------------------------------------------------------------------------
__global__ void __launch_bounds__(256) pack3_kernel(const float* __restrict__ c3) {
    extern __shared__ float cub[];               // 6 * 2048 floats = 48 KB
    int pr = blockIdx.x;                          // 0..135 (I<=J ranges)
    int J = (int)((sqrtf(8.f * pr + 1.f) - 1.f) * 0.5f);
    while ((J + 1) * (J + 2) / 2 <= pr) J++;
    while (J * (J + 1) / 2 > pr) J--;
    int I = pr - J * (J + 1) / 2;
    int kr = blockIdx.y;                          // 0..31 (8-wide)
    const int i0 = I * 16, j0 = J * 16, k0 = kr * 8;
    const int t = threadIdx.x;
    const int il = t >> 4, jl = t & 15;
    const int i = i0 + il, j = j0 + jl;
    const bool valid = (i <= j);
    const int p = (j * (j + 1)) / 2 + i;
    float* outrow = g_c3p + (size_t)p * DIMS + k0;
    if (valid && kr == 0) g_pairIdx[p] = ((uint32_t)i << 16) | (uint32_t)j;

    if (k0 + 7 < j0) {
        if (valid) {
            float4 z = make_float4(0.f, 0.f, 0.f, 0.f);
            *(float4*)(outrow + 0) = z;
            *(float4*)(outrow + 4) = z;
        }
        return;
    }

    {
        const int W1[6] = { 16, 8, 16, 8, 16, 16 };
        const int W2[6] = { 8, 16, 8, 16, 16, 16 };
        const int BA[6] = { i0, i0, j0, j0, k0, k0 };
        const int BB[6] = { j0, k0, i0, k0, i0, j0 };
        const int BC[6] = { k0, j0, k0, i0, j0, i0 };
#pragma unroll
        for (int m = 0; m < 6; m++) {
            int d0, d1, d2;
            if (W2[m] == 8) { d2 = 0; d1 = t & 15; d0 = t >> 4; }
            else { d2 = (t & 1) * 8; int q = t >> 1;
                   d1 = q % W1[m]; d0 = q / W1[m]; }
            const float* src = c3 + (size_t)(BA[m] + d0) * 65536
                                  + (BB[m] + d1) * 256 + (BC[m] + d2);
            float* dst = cub + m * 2048 + t * 8;
            float4 v0 = *(const float4*)(src);
            float4 v1 = *(const float4*)(src + 4);
            *(float4*)(dst)     = v0;
            *(float4*)(dst + 4) = v1;
        }
    }
    __syncthreads();
    if (!valid) return;

    float S[8];
#pragma unroll
    for (int kl = 0; kl < 8; kl++) {
        int k = k0 + kl;
        float s;
        if (k < j) {
            s = 0.f;
        } else {
            float C1 = cub[0 * 2048 + (il * 16 + jl) * 8 + kl];     // c3[i,j,k]
            if (k == j) {
                if (i == j) s = C1;
                else s = C1
                       + cub[2 * 2048 + (jl * 16 + il) * 8 + kl]    // c3[j,i,k]
                       + cub[3 * 2048 + (jl * 8 + kl) * 16 + il];   // c3[j,k,i]
            } else {
                float C2 = cub[1 * 2048 + (il * 8 + kl) * 16 + jl];   // c3[i,k,j]
                float C5 = cub[4 * 2048 + (kl * 16 + il) * 16 + jl];  // c3[k,i,j]
                if (i == j) s = C1 + C2 + C5;
                else s = C1 + C2 + C5
                       + cub[2 * 2048 + (jl * 16 + il) * 8 + kl]
                       + cub[3 * 2048 + (jl * 8 + kl) * 16 + il]
                       + cub[5 * 2048 + (kl * 16 + jl) * 16 + il];    // c3[k,j,i]
            }
        }
        S[kl] = f2tf32f(s);
    }
    *(float4*)(outrow + 0) = *(float4*)&S[0];
    *(float4*)(outrow + 4) = *(float4*)&S[4];
}

// ---------------------------------------------------------------------------
// extras: c2 rows (weight r_j*1), c1 row (1*1), zero pads — full K support.
// ---------------------------------------------------------------------------
__global__ void extras_kernel(const float* __restrict__ c2,
                              const float* __restrict__ c1) {
    int r = blockIdx.x;            // 0..383
    int k = threadIdx.x;           // 0..255
    int p = NPAIR + r;
    float v;
    uint32_t pidx;
    if (r < 256)      { v = c2[r * DIMS + k]; pidx = (256u << 16) | (uint32_t)r; }
    else if (r == 256){ v = c1[k];            pidx = (256u << 16) | 256u; }
    else              { v = 0.f;              pidx = (256u << 16) | 256u; }
    g_c3p[(size_t)p * DIMS + k] = f2tf32f(v);
    if (k == 0) g_pairIdx[p] = pidx;
}

// ---------------------------------------------------------------------------
// Main: 512 thr, 16 warps 2Mx8N (64x32 warp tiles), ragged-K chunk skipping.
// A: cp.async 3-stage ring of 64KB CHUNK-PAIRS -> one barrier per 2 chunks.
// B: direct GMEM fragments, double-buffered one k16 ahead.
// ---------------------------------------------------------------------------
__global__ void __launch_bounds__(THREADS) taylor_mma_kernel(
    float* __restrict__ out) {

    extern __shared__ char smem[];
    const uint32_t sb = smem_u32(smem);
    float* sred = (float*)(smem + 3 * PSTAGE_BYTES);

    const int tid  = threadIdx.x;
    const int lane = tid & 31, wid = tid >> 5;
    const int warpM = wid & 1, warpN = wid >> 1;   // 2 x 8 warps
    const int g = lane >> 2, tig = lane & 3;

    int tile = blockIdx.x - 3;                     // extras tiles first (LPT)
    if (tile < 0) tile += 260;
    const int p0 = tile * BM;
    const int b0 = blockIdx.y * BN;

    int c0 = 0;
    if (tile < 257) {
        int r0 = tile * BM;
        int j0 = (int)((sqrtf(8.f * r0 + 1.f) - 1.f) * 0.5f);
        while ((j0 + 1) * (j0 + 2) / 2 <= r0) j0++;
        while (j0 * (j0 + 1) / 2 > r0) j0--;
        c0 = j0 >> 5;
    }
    const int P0 = c0 >> 1;                        // first chunk-pair

    if (tid < BN) sred[tid] = 0.f;

    // ---- A cp.async coords (512 thr => 2 cp16/thread per 16KB chunk) ----
    const float* Ag = g_c3p + (size_t)p0 * DIMS;
    uint32_t cpdst[2];
    const float* cpsrc[2];
#pragma unroll
    for (int it = 0; it < 2; it++) {
        int idx = tid + it * THREADS;
        int row = idx >> 3, seg = idx & 7;
        cpdst[it] = row * 128 + ((seg ^ (row & 7)) << 4);
        cpsrc[it] = Ag + (size_t)row * DIMS + seg * 4;
    }
    // load chunk-pair P (chunks 2P, 2P+1) into ring stage P%3
    auto cp_pair = [&](int P) {
        const uint32_t s = sb + (P % 3) * PSTAGE_BYTES;
#pragma unroll
        for (int h = 0; h < 2; h++) {
            const int k0 = (2 * P + h) * 32;
#pragma unroll
            for (int it = 0; it < 2; it++)
                cp16(s + h * CHUNK_BYTES + cpdst[it], cpsrc[it] + k0);
        }
    };

    const uint4* bptr = (const uint4*)g_relf
                      + ((size_t)(b0 >> 3) + warpN * 4) * 512 + lane;

    int aoff[4], axor[4];
#pragma unroll
    for (int msl = 0; msl < 4; msl++) {
        int rowA = warpM * 64 + msl * 16 + ((lane >> 3) & 1) * 8 + (lane & 7);
        aoff[msl] = rowA * 128;
        axor[msl] = rowA & 7;
    }
    const int kcA = (lane >> 4) & 1;

    float acc[4][4][4];
#pragma unroll
    for (int m = 0; m < 4; m++)
#pragma unroll
        for (int n = 0; n < 4; n++)
#pragma unroll
            for (int r = 0; r < 4; r++) acc[m][n][r] = 0.f;

    uint4 Bb0[4], Bb1[4];

    // prologue: 2 pair-groups in flight
    cp_pair(P0); CP_COMMIT();
    if (P0 + 1 < 4) cp_pair(P0 + 1);
    CP_COMMIT();

#define LDB(BB, kp)                                                           \
    do {                                                                      \
        _Pragma("unroll")                                                     \
        for (int nsl_ = 0; nsl_ < 4; nsl_++)                                  \
            (BB)[nsl_] = __ldg(bptr + nsl_ * 512 + (kp) * 32);                \
    } while (0)

#define COMPUTE_KP(As, KSBASE, BB)                                            \
    do {                                                                      \
        _Pragma("unroll")                                                     \
        for (int ks2 = 0; ks2 < 2; ++ks2) {                                   \
            const int ks = (KSBASE) + ks2;                                    \
            uint32_t a[4][4];                                                 \
            _Pragma("unroll")                                                 \
            for (int msl = 0; msl < 4; ++msl)                                 \
                LDSM4(a[msl], (As) + aoff[msl] +                              \
                      ((((ks << 1) | kcA) ^ axor[msl]) << 4));                \
            _Pragma("unroll")                                                 \
            for (int nsl = 0; nsl < 4; ++nsl) {                               \
                uint32_t b0v = ks2 ? (BB)[nsl].z : (BB)[nsl].x;               \
                uint32_t b1v = ks2 ? (BB)[nsl].w : (BB)[nsl].y;               \
                _Pragma("unroll")                                             \
                for (int msl = 0; msl < 4; ++msl)                             \
                    MMA_TF32(acc[msl][nsl], a[msl][0], a[msl][1],             \
                             a[msl][2], a[msl][3], b0v, b1v);                 \
            }                                                                 \
        }                                                                     \
    } while (0)

    LDB(Bb0, 2 * c0);

    for (int P = P0; P < 4; ++P) {
        CP_WAIT(1);
        __syncthreads();                 // one barrier per 2 chunks
        if (P + 2 < 4) cp_pair(P + 2);   // refill stage freed last iteration
        CP_COMMIT();

        const uint32_t Sbase = sb + (P % 3) * PSTAGE_BYTES;
        const int ccs = (P == P0) ? c0 : 2 * P;
        for (int cc = ccs; cc <= 2 * P + 1; ++cc) {
            const uint32_t As = Sbase + (cc & 1) * CHUNK_BYTES;
            const int s0 = 2 * cc;
            LDB(Bb1, s0 + 1);
            COMPUTE_KP(As, 0, Bb0);
            if (cc + 1 < 8) LDB(Bb0, s0 + 2);
            COMPUTE_KP(As, 2, Bb1);
        }
    }

    // ---- epilogue: sred[col] += sum_m D[m,col] * r_i(m)[b] * r_j(m)[b] ----
    const float* wi[4][2];
    const float* wj[4][2];
#pragma unroll
    for (int msl = 0; msl < 4; ++msl)
#pragma unroll
        for (int h = 0; h < 2; ++h) {
            int rloc = warpM * 64 + msl * 16 + h * 8 + g;
            uint32_t pij = g_pairIdx[p0 + rloc];
            wi[msl][h] = g_relT + (size_t)(pij >> 16) * BATCH + b0;
            wj[msl][h] = g_relT + (size_t)(pij & 0xFFFF) * BATCH + b0;
        }

#pragma unroll
    for (int nsl = 0; nsl < 4; ++nsl) {
        const int coln = warpN * 32 + nsl * 8 + tig * 2;
        float s0 = 0.f, s1 = 0.f;
#pragma unroll
        for (int msl = 0; msl < 4; ++msl) {
#pragma unroll
            for (int h = 0; h < 2; ++h) {
                float2 aw = *(const float2*)(wi[msl][h] + coln);
                float2 bw = *(const float2*)(wj[msl][h] + coln);
                s0 += acc[msl][nsl][2 * h]     * aw.x * bw.x;
                s1 += acc[msl][nsl][2 * h + 1] * aw.y * bw.y;
            }
        }
#pragma unroll
        for (int o = 4; o <= 16; o <<= 1) {
            s0 += __shfl_xor_sync(0xFFFFFFFFu, s0, o);
            s1 += __shfl_xor_sync(0xFFFFFFFFu, s1, o);
        }
        if (g == 0) {
            atomicAdd(&sred[coln],     s0);
            atomicAdd(&sred[coln + 1], s1);
        }
    }
    __syncthreads();

    if (tid < BN) atomicAdd(out + b0 + tid, sred[tid]);
}

// ---------------------------------------------------------------------------
extern "C" void kernel_launch(void* const* d_in, const int* in_sizes, int n_in,
                              void* d_out, int out_size) {
    const float* x       = (const float*)d_in[0];
    const float* offsets = (const float*)d_in[1];
    const float* coeff0  = (const float*)d_in[2];
    const float* coeff1  = (const float*)d_in[3];
    const float* coeff2  = (const float*)d_in[4];
    const float* coeff3  = (const float*)d_in[5];
    float* out = (float*)d_out;

    cudaFuncSetAttribute(taylor_mma_kernel,
                         cudaFuncAttributeMaxDynamicSharedMemorySize, SMEM_BYTES);
    cudaFuncSetAttribute(pack3_kernel,
                         cudaFuncAttributeMaxDynamicSharedMemorySize, 49152);

    prep_rel_kernel<<<((DIMS + 1) * BATCH) / 256, 256>>>(x, offsets, coeff0, out);

    dim3 pgrid(136, 32);
    pack3_kernel<<<pgrid, 256, 49152>>>(coeff3);
    extras_kernel<<<384, 256>>>(coeff2, coeff1);

    dim3 grid(NROWS / BM, BATCH / BN);   // (260, 8)
    taylor_mma_kernel<<<grid, THREADS, SMEM_BYTES>>>(out);
}